// round 4
// baseline (speedup 1.0000x reference)
#include <cuda_runtime.h>
#include <stdint.h>

// FloodPath: 16-step binary flood fill, bit-packed CA, fully fused.
// Register-walking redesign: guard-ring padded smem (no boundary predicates,
// no index math), vertical register rolling (17 LDS / 5 words), count adder
// fused into the step, shrinking active window, MLP-unrolled ballot pack.

#define HW    4096
#define CORE  256
#define HALO  32
#define PADR  320              // active padded rows (core + 2*HALO)
#define SW    12               // words/row: guard + 10 active + guard
#define NROWS 322              // guard + 320 + guard
#define NW    (NROWS * SW)     // 3864
#define NT    640
#define NCOL  10
#define RPT   5                // rows per thread (320 / 64 groups)
#define STEPS 16

__global__ void __launch_bounds__(NT)
flood_kernel(const float2* __restrict__ in, float* __restrict__ out)
{
    __shared__ uint32_t sm_free[NW];
    __shared__ uint32_t sm_a[NW];
    __shared__ uint32_t sm_b[NW];

    const int tid  = threadIdx.x;
    const int lane = tid & 31;
    const int warp = tid >> 5;
    const int tile_x = (blockIdx.x & 15) * CORE;
    const int tile_y = (blockIdx.x >> 4) * CORE;

    // ---- pack: one word per warp via ballot; unrolled for load MLP.
    // smem row r: 0 guard, 1..320 active (padded row p = r-1), 321 guard.
    // col c: 0 guard, 1..10 active, 11 guard.
#pragma unroll 4
    for (int w = warp; w < NW; w += NT / 32) {
        int r = w / SW;
        int c = w - r * SW;
        uint32_t freeb = 0u, fldb = 0u;
        if (r >= 1 && r <= PADR && c >= 1 && c <= NCOL) {   // warp-uniform
            int gy = tile_y - HALO + (r - 1);
            int gx = tile_x - HALO + (c - 1) * 32 + lane;
            bool inr = ((unsigned)gy < HW) && ((unsigned)gx < HW);
            float2 v = make_float2(1.f, 0.f);               // outside = wall
            if (inr) v = in[(size_t)gy * HW + gx];
            freeb = __ballot_sync(0xffffffffu, inr && (v.x == 0.f));
            fldb  = __ballot_sync(0xffffffffu, inr && (v.y != 0.f));
        }
        if (lane == 0) { sm_free[w] = freeb; sm_a[w] = fldb; sm_b[w] = 0u; }
    }
    __syncthreads();

    // ---- thread ownership: column c (1..10), padded rows p0..p0+4
    const int c  = tid % NCOL + 1;
    const int g  = tid / NCOL;          // 0..63
    const int p0 = g * RPT;             // padded row of first owned word
    const int base = (1 + p0) * SW + c; // smem index of first owned word

    uint32_t fr[RPT];
#pragma unroll
    for (int k = 0; k < RPT; k++) fr[k] = sm_free[base + k * SW];

    uint32_t cnt0[RPT], cnt1[RPT], cnt2[RPT], cnt3[RPT], cnt4[RPT];
#pragma unroll
    for (int k = 0; k < RPT; k++) {
        cnt0[k] = cnt1[k] = cnt2[k] = cnt3[k] = cnt4[k] = 0u;
    }

    uint32_t* src = sm_a;
    uint32_t* dst = sm_b;

#pragma unroll 1
    for (int s = 1; s <= STEPS; s++) {
        // rows that can still influence core output after this step
        const int lo_p = 16 + s;        // inclusive, padded-row space
        const int hi_p = 304 - s;       // exclusive

        uint32_t up = src[base - SW];   // row p0-1 (guard row = 0 for g==0)
        uint32_t ss = src[base];
#pragma unroll
        for (int k = 0; k < RPT; k++) {
            uint32_t dn = src[base + (k + 1) * SW];  // guard row = 0 at bottom
            int p = p0 + k;
            if (p >= lo_p && p < hi_p) {
                uint32_t lf = src[base + k * SW - 1];  // guard col = 0
                uint32_t rt = src[base + k * SW + 1];  // guard col = 0
                uint32_t nf = (ss | up | dn
                              | (ss << 1) | (lf >> 31)
                              | (ss >> 1) | (rt << 31)) & fr[k];
                dst[base + k * SW] = nf;
                if (p >= HALO && p < HALO + CORE) {     // count core rows only
                    uint32_t carry = nf, t;
                    t = cnt0[k] & carry; cnt0[k] ^= carry; carry = t;
                    t = cnt1[k] & carry; cnt1[k] ^= carry; carry = t;
                    t = cnt2[k] & carry; cnt2[k] ^= carry; carry = t;
                    t = cnt3[k] & carry; cnt3[k] ^= carry; carry = t;
                    cnt4[k] ^= carry;
                }
            }
            up = ss; ss = dn;
        }
        __syncthreads();
        uint32_t* tmp = src; src = dst; dst = tmp;
    }
    // final flood lives in src

    // ---- unpack: owner thread expands its core words to [occ, flood, count]
    if (c >= 2 && c <= 9) {
#pragma unroll
        for (int k = 0; k < RPT; k++) {
            int p = p0 + k;
            if (p < HALO || p >= HALO + CORE) continue;
            uint32_t fw  = src[base + k * SW];
            uint32_t frk = fr[k];
            int gy  = tile_y + (p - HALO);
            int gx0 = tile_x + (c - 2) * 32;
            float4* o4 = (float4*)(out + ((size_t)gy * HW + gx0) * 3);
#pragma unroll
            for (int j = 0; j < 24; j++) {   // 32 cells * 3 ch = 24 float4
                float4 v;
                float* e = (float*)&v;
#pragma unroll
                for (int q = 0; q < 4; q++) {
                    int m  = j * 4 + q;
                    int b  = m / 3;          // cell bit   (compile-time)
                    int ch = m - b * 3;      // channel    (compile-time)
                    float val;
                    if (ch == 0) {
                        val = ((frk >> b) & 1u) ? 0.0f : 1.0f;  // occupied
                    } else if (ch == 1) {
                        val = ((fw >> b) & 1u) ? 1.0f : 0.0f;   // flood
                    } else {
                        uint32_t cc =  ((cnt0[k] >> b) & 1u)
                                    | (((cnt1[k] >> b) & 1u) << 1)
                                    | (((cnt2[k] >> b) & 1u) << 2)
                                    | (((cnt3[k] >> b) & 1u) << 3)
                                    | (((cnt4[k] >> b) & 1u) << 4);
                        val = (float)cc;                        // count 0..16
                    }
                    e[q] = val;
                }
                o4[j] = v;
            }
        }
    }
}

extern "C" void kernel_launch(void* const* d_in, const int* in_sizes, int n_in,
                              void* d_out, int out_size)
{
    const float2* in  = (const float2*)d_in[0]; // flood_input [H,W,2] f32
    float*        out = (float*)d_out;          // [H,W,3] f32
    (void)in_sizes; (void)n_in; (void)out_size;
    flood_kernel<<<256, NT>>>(in, out);
}

// round 5
// speedup vs baseline: 1.3221x; 1.3221x over previous
#include <cuda_runtime.h>
#include <stdint.h>

// FloodPath: 16-step binary flood fill, bit-packed, L2-resident ping-pong.
// pack (ballot) -> 16 global step kernels (uint4 per thread) -> unpack+count.

#define HW    4096
#define WPR   128                 // 32-bit words per row
#define NWORD (HW * WPR)          // 524288 words = 2 MB per plane
#define STEPS 16

__device__ uint32_t g_free[NWORD];              // bit=1: cell is free
__device__ uint32_t g_plane[STEPS + 1][NWORD];  // flood after step t

// ---- pack: warp ballots 32 cells -> 1 word. 16384 warps, 32 words each.
__global__ void __launch_bounds__(256)
pack_kernel(const float2* __restrict__ in)
{
    const int warp = (blockIdx.x * 256 + threadIdx.x) >> 5;
    const int lane = threadIdx.x & 31;
    const int w0   = warp * 32;
#pragma unroll 4
    for (int i = 0; i < 32; i++) {
        int w = w0 + i;
        float2 v = in[(size_t)w * 32 + lane];   // cell = w*32 + lane
        uint32_t fr = __ballot_sync(0xffffffffu, v.x == 0.f);
        uint32_t fl = __ballot_sync(0xffffffffu, v.y != 0.f);
        if (lane == 0) { g_free[w] = fr; g_plane[0][w] = fl; }
    }
}

// ---- one flood step: thread computes 4 consecutive words (one uint4).
__global__ void __launch_bounds__(256)
step_kernel(int t)
{
    const uint32_t* __restrict__ src = g_plane[t - 1];
    uint32_t*       __restrict__ dst = g_plane[t];

    const int g  = blockIdx.x * 256 + threadIdx.x;   // 0..131071 uint4 groups
    const int y  = g >> 5;                           // row
    const int xg = g & 31;                           // uint4 group in row
    const int b  = y * WPR + xg * 4;                 // first word index

    const uint4 z  = make_uint4(0u, 0u, 0u, 0u);
    const uint4 s  = *(const uint4*)(src + b);
    const uint4 up = (y > 0)      ? *(const uint4*)(src + b - WPR) : z;
    const uint4 dn = (y < HW - 1) ? *(const uint4*)(src + b + WPR) : z;
    const uint32_t lf = (xg > 0)  ? src[b - 1] : 0u;   // word left of group
    const uint32_t rt = (xg < 31) ? src[b + 4] : 0u;   // word right of group
    const uint4 fr = *(const uint4*)(g_free + b);

    // left neighbor = bit-1 (s<<1, prev word bit31 in via >>31)
    // right neighbor = bit+1 (s>>1, next word bit0 in via <<31)
    uint4 o;
    o.x = (s.x | up.x | dn.x | (s.x << 1) | (lf  >> 31) | (s.x >> 1) | (s.y << 31)) & fr.x;
    o.y = (s.y | up.y | dn.y | (s.y << 1) | (s.x >> 31) | (s.y >> 1) | (s.z << 31)) & fr.y;
    o.z = (s.z | up.z | dn.z | (s.z << 1) | (s.y >> 31) | (s.z >> 1) | (s.w << 31)) & fr.z;
    o.w = (s.w | up.w | dn.w | (s.w << 1) | (s.z >> 31) | (s.w >> 1) | (rt  << 31)) & fr.w;
    *(uint4*)(dst + b) = o;
}

// ---- unpack: thread-per-word. Count via 5-bit-plane ripple adder over the
// 16 stored planes, then expand 32 cells to [occ, flood, count] floats.
__global__ void __launch_bounds__(256)
unpack_kernel(float* __restrict__ out)
{
    const int w = blockIdx.x * 256 + threadIdx.x;    // word id
    const uint32_t fr = g_free[w];
    const uint32_t fw = g_plane[STEPS][w];

    uint32_t c0 = 0u, c1 = 0u, c2 = 0u, c3 = 0u, c4 = 0u;
#pragma unroll
    for (int t = 1; t <= STEPS; t++) {
        uint32_t carry = g_plane[t][w], x;
        x = c0 & carry; c0 ^= carry; carry = x;
        x = c1 & carry; c1 ^= carry; carry = x;
        x = c2 & carry; c2 ^= carry; carry = x;
        x = c3 & carry; c3 ^= carry; carry = x;
        c4 ^= carry;
    }

    float4* o4 = (float4*)(out + (size_t)w * 96);    // 32 cells * 3 floats
#pragma unroll
    for (int j = 0; j < 24; j++) {
        float4 v;
        float* e = (float*)&v;
#pragma unroll
        for (int k = 0; k < 4; k++) {
            const int m  = j * 4 + k;
            const int b  = m / 3;        // cell   (compile-time)
            const int ch = m - b * 3;    // channel(compile-time)
            float val;
            if (ch == 0) {
                val = ((fr >> b) & 1u) ? 0.0f : 1.0f;    // occupied
            } else if (ch == 1) {
                val = ((fw >> b) & 1u) ? 1.0f : 0.0f;    // flood
            } else {
                uint32_t c =  ((c0 >> b) & 1u)
                           | (((c1 >> b) & 1u) << 1)
                           | (((c2 >> b) & 1u) << 2)
                           | (((c3 >> b) & 1u) << 3)
                           | (((c4 >> b) & 1u) << 4);
                val = (float)c;                          // count 0..16
            }
            e[k] = val;
        }
        o4[j] = v;
    }
}

extern "C" void kernel_launch(void* const* d_in, const int* in_sizes, int n_in,
                              void* d_out, int out_size)
{
    const float2* in  = (const float2*)d_in[0];  // flood_input [H,W,2] f32
    float*        out = (float*)d_out;           // [H,W,3] f32
    (void)in_sizes; (void)n_in; (void)out_size;

    pack_kernel<<<2048, 256>>>(in);              // 16384 warps, 32 words each
    for (int t = 1; t <= STEPS; t++)
        step_kernel<<<512, 256>>>(t);            // 128K uint4 groups
    unpack_kernel<<<2048, 256>>>(out);           // 512K words
}

// round 6
// speedup vs baseline: 2.8110x; 2.1263x over previous
#include <cuda_runtime.h>
#include <stdint.h>

// FloodPath: 16-step binary flood fill, bit-packed, L2-resident ping-pong.
// R6: step = single-wave 128x1024, warp-per-row with shfl word-neighbors;
//     unpack = shfl-broadcast expansion for coalesced stores.

#define HW    4096
#define WPR   128                 // 32-bit words per row
#define NWORD (HW * WPR)          // 524288 words = 2 MB per plane
#define STEPS 16

__device__ uint32_t g_free[NWORD];              // bit=1: cell is free
__device__ uint32_t g_plane[STEPS + 1][NWORD];  // flood after step t

// ---- pack: warp ballots 32 cells -> 1 word. 16384 warps, 32 words each.
__global__ void __launch_bounds__(256)
pack_kernel(const float2* __restrict__ in)
{
    const int warp = (blockIdx.x * 256 + threadIdx.x) >> 5;
    const int lane = threadIdx.x & 31;
    const int w0   = warp * 32;
#pragma unroll 4
    for (int i = 0; i < 32; i++) {
        int w = w0 + i;
        float2 v = in[(size_t)w * 32 + lane];   // cell = w*32 + lane
        uint32_t fr = __ballot_sync(0xffffffffu, v.x == 0.f);
        uint32_t fl = __ballot_sync(0xffffffffu, v.y != 0.f);
        if (lane == 0) { g_free[w] = fr; g_plane[0][w] = fl; }
    }
}

// ---- one flood step: warp = one full row (32 lanes x 4 words = 128 words).
// 131072 threads = 128 blocks x 1024 = exactly one wave.
__global__ void __launch_bounds__(1024)
step_kernel(int t)
{
    const uint32_t* __restrict__ src = g_plane[t - 1];
    uint32_t*       __restrict__ dst = g_plane[t];

    const int g    = blockIdx.x * 1024 + threadIdx.x; // uint4 group id
    const int y    = g >> 5;                          // row
    const int lane = threadIdx.x & 31;
    const int b    = g * 4;                           // first word index

    const uint4 z  = make_uint4(0u, 0u, 0u, 0u);
    const uint4 s  = *(const uint4*)(src + b);
    const uint4 up = (y > 0)      ? *(const uint4*)(src + b - WPR) : z;
    const uint4 dn = (y < HW - 1) ? *(const uint4*)(src + b + WPR) : z;
    const uint4 fr = *(const uint4*)(g_free + b);

    // word-neighbors across lanes within the row (row edges -> 0)
    uint32_t lf = __shfl_up_sync(0xffffffffu, s.w, 1);
    uint32_t rt = __shfl_down_sync(0xffffffffu, s.x, 1);
    if (lane == 0)  lf = 0u;
    if (lane == 31) rt = 0u;

    uint4 o;
    o.x = (s.x | up.x | dn.x | __funnelshift_l(lf,  s.x, 1)
                             | __funnelshift_r(s.x, s.y, 1)) & fr.x;
    o.y = (s.y | up.y | dn.y | __funnelshift_l(s.x, s.y, 1)
                             | __funnelshift_r(s.y, s.z, 1)) & fr.y;
    o.z = (s.z | up.z | dn.z | __funnelshift_l(s.y, s.z, 1)
                             | __funnelshift_r(s.z, s.w, 1)) & fr.z;
    o.w = (s.w | up.w | dn.w | __funnelshift_l(s.z, s.w, 1)
                             | __funnelshift_r(s.w, rt,  1)) & fr.w;
    *(uint4*)(dst + b) = o;
}

// ---- unpack: lane owns word w0+lane (coalesced loads + ripple adder),
// then shfl-broadcast each of the warp's 32 words; lane = cell bit,
// emitting 3 floats into a contiguous 384B span per word.
__global__ void __launch_bounds__(256)
unpack_kernel(float* __restrict__ out)
{
    const int w    = blockIdx.x * 256 + threadIdx.x;  // this lane's word
    const int lane = threadIdx.x & 31;
    const int w0   = w - lane;                        // warp's first word

    const uint32_t fr = g_free[w];
    const uint32_t fw = g_plane[STEPS][w];

    uint32_t c0 = 0u, c1 = 0u, c2 = 0u, c3 = 0u, c4 = 0u;
#pragma unroll
    for (int t = 1; t <= STEPS; t++) {
        uint32_t carry = g_plane[t][w], x;
        x = c0 & carry; c0 ^= carry; carry = x;
        x = c1 & carry; c1 ^= carry; carry = x;
        x = c2 & carry; c2 ^= carry; carry = x;
        x = c3 & carry; c3 ^= carry; carry = x;
        c4 ^= carry;
    }

#pragma unroll
    for (int k = 0; k < 32; k++) {
        const uint32_t bfr = __shfl_sync(0xffffffffu, fr, k);
        const uint32_t bfw = __shfl_sync(0xffffffffu, fw, k);
        const uint32_t b0  = __shfl_sync(0xffffffffu, c0, k);
        const uint32_t b1  = __shfl_sync(0xffffffffu, c1, k);
        const uint32_t b2  = __shfl_sync(0xffffffffu, c2, k);
        const uint32_t b3  = __shfl_sync(0xffffffffu, c3, k);
        const uint32_t b4  = __shfl_sync(0xffffffffu, c4, k);

        const float occ = (float)(((bfr >> lane) & 1u) ^ 1u);
        const float fld = (float)((bfw >> lane) & 1u);
        const uint32_t c =  ((b0 >> lane) & 1u)
                         | (((b1 >> lane) & 1u) << 1)
                         | (((b2 >> lane) & 1u) << 2)
                         | (((b3 >> lane) & 1u) << 3)
                         | (((b4 >> lane) & 1u) << 4);
        const float cnt = (float)c;

        float* o = out + (size_t)(w0 + k) * 96 + lane * 3;
        o[0] = occ;
        o[1] = fld;
        o[2] = cnt;
    }
}

extern "C" void kernel_launch(void* const* d_in, const int* in_sizes, int n_in,
                              void* d_out, int out_size)
{
    const float2* in  = (const float2*)d_in[0];  // flood_input [H,W,2] f32
    float*        out = (float*)d_out;           // [H,W,3] f32
    (void)in_sizes; (void)n_in; (void)out_size;

    pack_kernel<<<2048, 256>>>(in);              // 16384 warps, 32 words each
    for (int t = 1; t <= STEPS; t++)
        step_kernel<<<128, 1024>>>(t);           // 1 wave, warp = one row
    unpack_kernel<<<2048, 256>>>(out);           // 512K words
}